// round 9
// baseline (speedup 1.0000x reference)
#include <cuda_runtime.h>
#include <cuda_bf16.h>
#include <cstdint>

// ExpertCapacityBuffer: N tokens, TOP_K=2, 64 experts.
// capacity = ceil(1.25*N*2/64). Flat slot-major: f = slot*N + tok.
// rank(f) = #{g<f : expert(g)==expert(f)}; keep iff rank < capacity.
//
// Tiling: token tiles of EPT=512. g_cnt row r in [0,nbt) = slot0 of tile r;
// row nbt+r = slot1 of tile r. Row-major row order == flat order.
// k_count: per-row histograms.  k_scan: exclusive prefixes -> g_off.
// k_apply: offsets + in-tile match ranks -> capped weights, indices, mask.

#define NE   64
#define NEP  65              // padded row kills smem bank conflicts
#define TPB  512
#define EPT  512
#define NW   16              // warps per block
#define MAXROWS 4096

__device__ int g_cnt[MAXROWS][NE];
__device__ int g_off[MAXROWS][NE];

// warp-0 dtype probe: int64 values <64 => odd 32-bit words zero (first 256B).
__device__ __forceinline__ void probe_w0(const void* eraw, int lane, int* s_is64) {
    if (threadIdx.x < 32) {
        unsigned x = ((const unsigned*)eraw)[2 * lane + 1];
        unsigned nz = __ballot_sync(0xFFFFFFFFu, x != 0u);
        if (lane == 0) *s_is64 = (nz == 0u);
    }
}

// ---------------- Kernel 1: per-row expert histograms ----------------
__global__ void __launch_bounds__(TPB, 4)
k_count(const void* __restrict__ eraw, int n_tok, int nbt) {
    __shared__ int hA[NW][NEP];
    __shared__ int hB[NW][NEP];
    __shared__ int s_is64;
    const int t = threadIdx.x, b = blockIdx.x;
    const int warp = t >> 5, lane = t & 31;
    const unsigned lt = (1u << lane) - 1u;

    const int tok = b * EPT + t;
    const bool valid = tok < n_tok;

    int2 v32 = make_int2(0, 0);
    if (valid) v32 = __ldg((const int2*)eraw + tok);      // eager

    for (int i = t; i < NW * NEP; i += TPB) { ((int*)hA)[i] = 0; ((int*)hB)[i] = 0; }
    probe_w0(eraw, lane, &s_is64);
    __syncthreads();

    int e0 = NE + lane, e1 = NE + lane;                    // unique keys if invalid
    if (valid) {
        if (s_is64) {
            longlong2 v = __ldg((const longlong2*)eraw + tok);
            e0 = (int)v.x & (NE - 1); e1 = (int)v.y & (NE - 1);
        } else {
            e0 = v32.x & (NE - 1); e1 = v32.y & (NE - 1);
        }
    }
    unsigned m0 = __match_any_sync(0xFFFFFFFFu, e0);
    unsigned m1 = __match_any_sync(0xFFFFFFFFu, e1);
    if (valid && !(m0 & lt)) hA[warp][e0] = __popc(m0);
    if (valid && !(m1 & lt)) hB[warp][e1] = __popc(m1);
    __syncthreads();

    // column reduce: each warp owns 8 expert-slot pairs; lanes 0..15 hold rows
    #pragma unroll
    for (int k = 0; k < 8; k++) {
        const int p = warp * 8 + k;          // 0..127
        const int e = p & (NE - 1);
        const bool isB = p >= NE;
        int v = (lane < NW) ? (isB ? hB[lane][e] : hA[lane][e]) : 0;
        #pragma unroll
        for (int d = 8; d > 0; d >>= 1) v += __shfl_xor_sync(0xFFFFFFFFu, v, d);
        v += __shfl_xor_sync(0xFFFFFFFFu, v, 16);
        if (lane == 0) g_cnt[isB ? (nbt + b) : b][e] = v;
    }
}

// ---------------- Kernel 2: exclusive scan over rows ----------------
#define SCAN_TPB 1024
#define NCH 16
__global__ void __launch_bounds__(SCAN_TPB)
k_scan(int rows) {
    __shared__ int part[NCH][NE];
    const int t = threadIdx.x;
    const int e = t & (NE - 1), c = t >> 6;
    const int rpc = (rows + NCH - 1) / NCH;
    const int r0 = c * rpc;

    if (rpc <= 32) {                          // fast path: rows <= 512
        int vals[32];
        #pragma unroll
        for (int i = 0; i < 32; i++) vals[i] = g_cnt[r0 + i][e];   // static array: safe
        int s = 0;
        #pragma unroll
        for (int i = 0; i < 32; i++)
            if (i < rpc && r0 + i < rows) s += vals[i];
        part[c][e] = s;
        __syncthreads();
        if (t < NE) {
            int run = 0;
            #pragma unroll
            for (int cc = 0; cc < NCH; cc++) { int v = part[cc][t]; part[cc][t] = run; run += v; }
        }
        __syncthreads();
        int run = part[c][e];
        #pragma unroll
        for (int i = 0; i < 32; i++) {
            int r = r0 + i;
            if (i < rpc && r < rows) { g_off[r][e] = run; run += vals[i]; }
        }
    } else {                                  // generic fallback
        const int r1 = min(r0 + rpc, rows);
        int s = 0;
        for (int r = r0; r < r1; r++) s += g_cnt[r][e];
        part[c][e] = s;
        __syncthreads();
        if (t < NE) {
            int run = 0;
            #pragma unroll
            for (int cc = 0; cc < NCH; cc++) { int v = part[cc][t]; part[cc][t] = run; run += v; }
        }
        __syncthreads();
        int run = part[c][e];
        for (int r = r0; r < r1; r++) { int v = g_cnt[r][e]; g_off[r][e] = run; run += v; }
    }
}

// ---------------- Kernel 3: ranks + outputs ----------------
// idx_mode: 0 none, 1 one-word (float), 2 int64
__global__ void __launch_bounds__(TPB, 4)
k_apply(const float* __restrict__ w, const void* __restrict__ eraw,
        int n_tok, int capacity, int nbt,
        float* __restrict__ out_w, void* __restrict__ out_idx, int idx_mode,
        float* __restrict__ out_mask) {
    __shared__ int hA[NW][NEP];
    __shared__ int hB[NW][NEP];
    __shared__ int offA[NE], offB[NE];
    __shared__ int s_is64;
    const int t = threadIdx.x, b = blockIdx.x;
    const int warp = t >> 5, lane = t & 31;
    const unsigned lt = (1u << lane) - 1u;

    const int tok = b * EPT + t;
    const bool valid = tok < n_tok;

    // eager loads
    int2 v32 = make_int2(0, 0);
    float2 wv = make_float2(0.f, 0.f);
    if (valid) {
        v32 = __ldg((const int2*)eraw + tok);
        wv  = __ldg((const float2*)w + tok);
    }
    if (t < NE)          offA[t] = g_off[b][t];
    else if (t < 2 * NE) offB[t - NE] = g_off[nbt + b][t - NE];

    for (int i = t; i < NW * NEP; i += TPB) { ((int*)hA)[i] = 0; ((int*)hB)[i] = 0; }
    probe_w0(eraw, lane, &s_is64);
    __syncthreads();

    int e0 = NE + lane, e1 = NE + lane;
    if (valid) {
        if (s_is64) {
            longlong2 v = __ldg((const longlong2*)eraw + tok);
            e0 = (int)v.x & (NE - 1); e1 = (int)v.y & (NE - 1);
        } else {
            e0 = v32.x & (NE - 1); e1 = v32.y & (NE - 1);
        }
    }
    unsigned m0 = __match_any_sync(0xFFFFFFFFu, e0);
    unsigned m1 = __match_any_sync(0xFFFFFFFFu, e1);
    const int wr0 = __popc(m0 & lt), wr1 = __popc(m1 & lt);
    if (valid && wr0 == 0) hA[warp][e0] = __popc(m0);
    if (valid && wr1 == 0) hB[warp][e1] = __popc(m1);
    __syncthreads();

    // 16-wide shfl exclusive scans over the 16 warp-rows; 8 pairs per warp
    #pragma unroll
    for (int k = 0; k < 8; k++) {
        const int p = warp * 8 + k;
        const int e = p & (NE - 1);
        const bool isB = p >= NE;
        int v = (lane < NW) ? (isB ? hB[lane][e] : hA[lane][e]) : 0;
        int x = v;
        #pragma unroll
        for (int d = 1; d < NW; d <<= 1) {
            int y = __shfl_up_sync(0xFFFFFFFFu, x, d);
            if (lane >= d) x += y;
        }
        if (lane < NW) { if (isB) hB[lane][e] = x - v; else hA[lane][e] = x - v; }
    }
    __syncthreads();

    if (valid) {
        const int rank0 = offA[e0] + hA[warp][e0] + wr0;
        const int rank1 = offB[e1] + hB[warp][e1] + wr1;
        const float w0 = (rank0 < capacity) ? wv.x : 0.0f;
        const float w1 = (rank1 < capacity) ? wv.y : 0.0f;
        ((float2*)out_w)[tok] = make_float2(w0, w1);
        if (idx_mode == 1) {
            ((float2*)out_idx)[tok] = make_float2((float)e0, (float)e1);
        } else if (idx_mode == 2) {
            longlong2 iv; iv.x = e0; iv.y = e1;
            ((longlong2*)out_idx)[tok] = iv;
        }
        if (out_mask) out_mask[tok] = ((w0 + w1) == 0.0f) ? 1.0f : 0.0f;
    }
}

extern "C" void kernel_launch(void* const* d_in, const int* in_sizes, int n_in,
                              void* d_out, int out_size) {
    const float* w    = (const float*)d_in[0];
    const void*  eidx = d_in[1];

    int flat  = in_sizes[0];                 // N * TOP_K
    int n_tok = flat / 2;
    int capacity = (flat * 5 + 255) / 256;   // ceil(1.25 * flat / 64)
    if (capacity < 1) capacity = 1;
    int nbt = (n_tok + EPT - 1) / EPT;
    if (2 * nbt > MAXROWS) nbt = MAXROWS / 2;   // guard (not hit at these sizes)
    int rows = 2 * nbt;

    float* out = (float*)d_out;
    float* out_w    = out;
    void*  out_idx  = nullptr;
    float* out_mask = nullptr;
    int idx_mode = 0;

    if (out_size >= 3 * flat + n_tok) {          // weights + i64 indices + mask
        idx_mode = 2; out_idx = out + flat; out_mask = out + 3 * flat;
    } else if (out_size >= 2 * flat + n_tok) {   // weights + 1-word indices + mask
        idx_mode = 1; out_idx = out + flat; out_mask = out + 2 * flat;
    } else if (out_size >= flat + n_tok) {       // weights + mask
        out_mask = out + flat;
    }

    k_count<<<nbt, TPB>>>(eidx, n_tok, nbt);
    k_scan<<<1, SCAN_TPB>>>(rows);
    k_apply<<<nbt, TPB>>>(w, eidx, n_tok, capacity, nbt,
                          out_w, out_idx, idx_mode, out_mask);
}

// round 10
// speedup vs baseline: 1.0225x; 1.0225x over previous
#include <cuda_runtime.h>
#include <cuda_bf16.h>
#include <cstdint>

// ExpertCapacityBuffer: N tokens, TOP_K=2, 64 experts.
// capacity = ceil(1.25*N*2/64). Flat slot-major: f = slot*N + tok.
// rank(f) = #{g<f : expert(g)==expert(f)}; keep iff rank < capacity.
//
// Two-level counts, two kernels, no scan pass:
//  k_count: super-block sb covers tiles {2sb, 2sb+1} (EPT=1024 tokens each).
//           Writes per-tile rows to g_cnt AND its chunk totals to g_chunk.
//  k_apply: offsets = sum of chunk rows < b/2 (+ <=1 partial tile row)
//           (+ slot0 grand total for slot1), gathered with MLP-friendly loads
//           and 16-lane shfl reduce; then in-tile match ranks + outputs.

#define NE   64
#define NEP  65              // padded row kills smem bank conflicts
#define TPB  1024
#define EPT  1024
#define TT   2               // tiles per count super-block
#define MAXROWS 4096         // g_cnt rows (2 * max tiles)
#define MAXCH   2048         // g_chunk rows (2 * max chunks)

__device__ int g_cnt[MAXROWS][NE];
__device__ int g_chunk[MAXCH][NE];

// warp-0 dtype probe: int64 values <64 => odd 32-bit words zero (first 256B).
__device__ __forceinline__ void probe_w0(const void* eraw, int lane, int* s_is64) {
    if (threadIdx.x < 32) {
        unsigned x = ((const unsigned*)eraw)[2 * lane + 1];
        unsigned nz = __ballot_sync(0xFFFFFFFFu, x != 0u);
        if (lane == 0) *s_is64 = (nz == 0u);
    }
}

// ---------------- Kernel 1: per-tile rows + per-superblock chunk totals ----------------
__global__ void __launch_bounds__(TPB)
k_count(const void* __restrict__ eraw, int n_tok, int nbt, int nsb) {
    __shared__ int hA[32][NEP];
    __shared__ int hB[32][NEP];
    __shared__ int s_is64;
    const int t = threadIdx.x, sb = blockIdx.x;
    const int warp = t >> 5, lane = t & 31;
    const unsigned lt = (1u << lane) - 1u;
    const int tile0 = sb * TT;

    // eager loads for both tiles
    int2 v32[TT];
    #pragma unroll
    for (int j = 0; j < TT; j++) {
        int tok = (tile0 + j) * EPT + t;
        v32[j] = (tile0 + j < nbt && tok < n_tok) ? __ldg((const int2*)eraw + tok)
                                                  : make_int2(0, 0);
    }
    probe_w0(eraw, lane, &s_is64);

    int acc[4] = {0, 0, 0, 0};       // chunk totals for this warp's 4 pairs

    #pragma unroll
    for (int j = 0; j < TT; j++) {
        if (tile0 + j >= nbt) break;                       // uniform per block
        for (int i = t; i < 32 * NEP; i += TPB) { ((int*)hA)[i] = 0; ((int*)hB)[i] = 0; }
        __syncthreads();

        const int tok = (tile0 + j) * EPT + t;
        const bool valid = tok < n_tok;
        int e0 = NE + lane, e1 = NE + lane;                // unique keys if invalid
        if (valid) {
            if (s_is64) {
                longlong2 v = __ldg((const longlong2*)eraw + tok);
                e0 = (int)v.x & (NE - 1); e1 = (int)v.y & (NE - 1);
            } else {
                e0 = v32[j].x & (NE - 1); e1 = v32[j].y & (NE - 1);
            }
        }
        unsigned m0 = __match_any_sync(0xFFFFFFFFu, e0);
        unsigned m1 = __match_any_sync(0xFFFFFFFFu, e1);
        if (valid && !(m0 & lt)) hA[warp][e0] = __popc(m0);
        if (valid && !(m1 & lt)) hB[warp][e1] = __popc(m1);
        __syncthreads();

        // column reduce: warp owns pairs p = warp*4+k (0..127)
        #pragma unroll
        for (int k = 0; k < 4; k++) {
            const int p = warp * 4 + k;
            const int e = p & (NE - 1);
            const bool isB = p >= NE;
            int v = isB ? hB[lane][e] : hA[lane][e];
            #pragma unroll
            for (int d = 16; d > 0; d >>= 1) v += __shfl_xor_sync(0xFFFFFFFFu, v, d);
            acc[k] += v;
            if (lane == 0) g_cnt[(isB ? nbt : 0) + tile0 + j][e] = v;
        }
        __syncthreads();
    }

    if (lane == 0) {
        #pragma unroll
        for (int k = 0; k < 4; k++) {
            const int p = warp * 4 + k;
            const int e = p & (NE - 1);
            const bool isB = p >= NE;
            g_chunk[(isB ? nsb : 0) + sb][e] = acc[k];
        }
    }
}

// ---------------- Kernel 2: offsets + ranks + outputs ----------------
// idx_mode: 0 none, 1 one-word (float), 2 int64
__global__ void __launch_bounds__(TPB)
k_apply(const float* __restrict__ w, const void* __restrict__ eraw,
        int n_tok, int capacity, int nbt, int nsb,
        float* __restrict__ out_w, void* __restrict__ out_idx, int idx_mode,
        float* __restrict__ out_mask) {
    __shared__ int hA[32][NEP];
    __shared__ int hB[32][NEP];
    __shared__ int offA[NE], offB[NE];
    __shared__ int s_is64;
    const int t = threadIdx.x, b = blockIdx.x;
    const int warp = t >> 5, lane = t & 31;
    const unsigned lt = (1u << lane) - 1u;

    const int tok = b * EPT + t;
    const bool valid = tok < n_tok;

    // eager data loads
    int2 v32 = make_int2(0, 0);
    float2 wv = make_float2(0.f, 0.f);
    if (valid) {
        v32 = __ldg((const int2*)eraw + tok);
        wv  = __ldg((const float2*)w + tok);
    }
    probe_w0(eraw, lane, &s_is64);

    // ---- offset gather (overlaps the eager DRAM loads) ----
    {
        const int e = t >> 4, c = t & 15;      // 16 threads per expert
        const int myc = b >> 1;                // chunk of this tile (TT=2)
        int aA = 0, aB = 0, tA = 0;
        #pragma unroll 4
        for (int cc = c; cc < nsb; cc += 16) {
            int vA = g_chunk[cc][e];
            int vB = g_chunk[nsb + cc][e];
            tA += vA;
            if (cc < myc) { aA += vA; aB += vB; }
        }
        if ((b & 1) && c == 0) {               // one partial tile row
            aA += g_cnt[b - 1][e];
            aB += g_cnt[nbt + b - 1][e];
        }
        #pragma unroll
        for (int d = 8; d > 0; d >>= 1) {      // 16-lane segment reduce
            aA += __shfl_down_sync(0xFFFFFFFFu, aA, d, 16);
            aB += __shfl_down_sync(0xFFFFFFFFu, aB, d, 16);
            tA += __shfl_down_sync(0xFFFFFFFFu, tA, d, 16);
        }
        if (c == 0) { offA[e] = aA; offB[e] = tA + aB; }
    }

    for (int i = t; i < 32 * NEP; i += TPB) { ((int*)hA)[i] = 0; ((int*)hB)[i] = 0; }
    __syncthreads();

    int e0 = NE + lane, e1 = NE + lane;
    if (valid) {
        if (s_is64) {
            longlong2 v = __ldg((const longlong2*)eraw + tok);
            e0 = (int)v.x & (NE - 1); e1 = (int)v.y & (NE - 1);
        } else {
            e0 = v32.x & (NE - 1); e1 = v32.y & (NE - 1);
        }
    }
    unsigned m0 = __match_any_sync(0xFFFFFFFFu, e0);
    unsigned m1 = __match_any_sync(0xFFFFFFFFu, e1);
    const int wr0 = __popc(m0 & lt), wr1 = __popc(m1 & lt);
    if (valid && wr0 == 0) hA[warp][e0] = __popc(m0);
    if (valid && wr1 == 0) hB[warp][e1] = __popc(m1);
    __syncthreads();

    // exclusive scans over 32 warp-rows: warp owns pairs p = warp*4+k
    #pragma unroll
    for (int k = 0; k < 4; k++) {
        const int p = warp * 4 + k;
        const int e = p & (NE - 1);
        const bool isB = p >= NE;
        int v = isB ? hB[lane][e] : hA[lane][e];
        int x = v;
        #pragma unroll
        for (int d = 1; d < 32; d <<= 1) {
            int y = __shfl_up_sync(0xFFFFFFFFu, x, d);
            if (lane >= d) x += y;
        }
        if (isB) hB[lane][e] = x - v; else hA[lane][e] = x - v;
    }
    __syncthreads();

    if (valid) {
        const int rank0 = offA[e0] + hA[warp][e0] + wr0;
        const int rank1 = offB[e1] + hB[warp][e1] + wr1;
        const float w0 = (rank0 < capacity) ? wv.x : 0.0f;
        const float w1 = (rank1 < capacity) ? wv.y : 0.0f;
        ((float2*)out_w)[tok] = make_float2(w0, w1);
        if (idx_mode == 1) {
            ((float2*)out_idx)[tok] = make_float2((float)e0, (float)e1);
        } else if (idx_mode == 2) {
            longlong2 iv; iv.x = e0; iv.y = e1;
            ((longlong2*)out_idx)[tok] = iv;
        }
        if (out_mask) out_mask[tok] = ((w0 + w1) == 0.0f) ? 1.0f : 0.0f;
    }
}

extern "C" void kernel_launch(void* const* d_in, const int* in_sizes, int n_in,
                              void* d_out, int out_size) {
    const float* w    = (const float*)d_in[0];
    const void*  eidx = d_in[1];

    int flat  = in_sizes[0];                 // N * TOP_K
    int n_tok = flat / 2;
    int capacity = (flat * 5 + 255) / 256;   // ceil(1.25 * flat / 64)
    if (capacity < 1) capacity = 1;
    int nbt = (n_tok + EPT - 1) / EPT;
    if (2 * nbt > MAXROWS) nbt = MAXROWS / 2;   // guard (not hit at these sizes)
    int nsb = (nbt + TT - 1) / TT;

    float* out = (float*)d_out;
    float* out_w    = out;
    void*  out_idx  = nullptr;
    float* out_mask = nullptr;
    int idx_mode = 0;

    if (out_size >= 3 * flat + n_tok) {          // weights + i64 indices + mask
        idx_mode = 2; out_idx = out + flat; out_mask = out + 3 * flat;
    } else if (out_size >= 2 * flat + n_tok) {   // weights + 1-word indices + mask
        idx_mode = 1; out_idx = out + flat; out_mask = out + 2 * flat;
    } else if (out_size >= flat + n_tok) {       // weights + mask
        out_mask = out + flat;
    }

    k_count<<<nsb, TPB>>>(eidx, n_tok, nbt, nsb);
    k_apply<<<nbt, TPB>>>(w, eidx, n_tok, capacity, nbt, nsb,
                          out_w, out_idx, idx_mode, out_mask);
}